// round 3
// baseline (speedup 1.0000x reference)
#include <cuda_runtime.h>
#include <math.h>

#define D_TOT 320
#define DZ    64
#define DX    256
#define DK    256          // dense k count (D_TOT - DZ)
#define HID   16
#define BATCH 1024
#define NEG   0.01f
#define HALF_LOG2PI 0.91893853320467274f

// scratch (device globals — no allocation allowed)
__device__ float g_E[D_TOT * D_TOT];                 // exp(-mask_param), [j][k]
__device__ float4 g_W0t[D_TOT * 4 * DK];             // W0 transposed: [j][h4][k'] float4, diag zeroed
__device__ float g_accum;                            // recons accumulator

__device__ __forceinline__ float lrelu(float v) { return fmaxf(v, NEG * v); }

__device__ __forceinline__ unsigned long long pack2(float lo, float hi) {
    unsigned long long r;
    asm("mov.b64 %0, {%1, %2};" : "=l"(r) : "f"(lo), "f"(hi));
    return r;
}
__device__ __forceinline__ void unpack2(unsigned long long v, float& lo, float& hi) {
    asm("mov.b64 {%0, %1}, %2;" : "=f"(lo), "=f"(hi) : "l"(v));
}
__device__ __forceinline__ void ffma2(unsigned long long& d, unsigned long long a,
                                      unsigned long long b) {
    asm("fma.rn.f32x2 %0, %1, %2, %0;" : "+l"(d) : "l"(a), "l"(b));
}

// ---------------------------------------------------------------------------
// Init: E = exp(-mask_param); W0 transpose to [j][h4][k'] with diag zeroed;
// std -> out; zero accumulator.
// ---------------------------------------------------------------------------
__global__ void init_kernel(const float* __restrict__ mp,
                            const float* __restrict__ W0,
                            const float* __restrict__ logvar,
                            float* __restrict__ out) {
    int i = blockIdx.x * blockDim.x + threadIdx.x;

    if (i < D_TOT * 4 * DK) {
        int kp = i & (DK - 1);           // k' 0..255
        int h4 = (i >> 8) & 3;           // which float4 of the 16 h's
        int j  = i >> 10;                // 0..319
        int k  = DZ + kp;
        float4 v;
        if (j == k) {
            v = make_float4(0.f, 0.f, 0.f, 0.f);
        } else {
            v = *(const float4*)(W0 + ((size_t)k * D_TOT + j) * HID + h4 * 4);
        }
        g_W0t[i] = v;
    }
    if (i < D_TOT * D_TOT) g_E[i] = expf(-mp[i]);
    if (i < D_TOT) out[1 + BATCH * D_TOT + i] = expf(0.5f * logvar[i]);
    if (i == 0) g_accum = 0.0f;
}

// ---------------------------------------------------------------------------
// Latent path: k < 64, only j == k contributes (fixed-mask self-link)
// ---------------------------------------------------------------------------
__global__ void latent_kernel(const float* __restrict__ z,
                              const float* __restrict__ u,
                              const float* __restrict__ W0,
                              const float* __restrict__ b0,
                              const float* __restrict__ W1,
                              const float* __restrict__ b1,
                              const float* __restrict__ W2,
                              const float* __restrict__ b2,
                              const float* __restrict__ logvar,
                              float* __restrict__ out) {
    int tid = blockIdx.x * blockDim.x + threadIdx.x;   // 65536 = 1024*64
    int k = tid & (DZ - 1);
    int b = tid >> 6;

    float uu = u[((size_t)b * D_TOT + k) * D_TOT + k];
    float E  = g_E[k * D_TOT + k];
    float s  = z[b * DZ + k];
    float denom = fmaf(1.0f - uu, E, uu);
    float m = __fdividef(uu * s, denom);

    float h1v[HID];
#pragma unroll
    for (int g = 0; g < HID; g++) h1v[g] = b1[k * HID + g];
#pragma unroll
    for (int h = 0; h < HID; h++) {
        float h0 = fmaf(m, W0[((size_t)k * D_TOT + k) * HID + h], b0[k * HID + h]);
        float a = lrelu(h0);
        const float* w1r = W1 + (k * HID + h) * HID;
#pragma unroll
        for (int g = 0; g < HID; g++) h1v[g] = fmaf(a, w1r[g], h1v[g]);
    }
    float mu = b2[k];
#pragma unroll
    for (int h = 0; h < HID; h++) mu = fmaf(lrelu(h1v[h]), W2[k * HID + h], mu);

    out[1 + (size_t)b * D_TOT + k] = mu;

    float logstd = 0.5f * logvar[k];
    float istd = __expf(-logstd);
    float diff = (s - mu) * istd;
    float lp = fmaf(-0.5f * diff, diff, -logstd - HALF_LOG2PI);

#pragma unroll
    for (int o = 16; o > 0; o >>= 1) lp += __shfl_down_sync(0xffffffffu, lp, o);
    if ((threadIdx.x & 31) == 0) atomicAdd(&g_accum, lp);
}

// ---------------------------------------------------------------------------
// Profiling alignment pads: make ncu's "-s 5 -c 1" land on dense_kernel.
// ---------------------------------------------------------------------------
__global__ void pad_kernel() {}

// ---------------------------------------------------------------------------
// Dense path: k in [64, 320). Block: 32 k' (lanes) x 16 b (8 warps x 2 b/thr)
// 2 b/thread keeps register demand well under the 128-reg cap (no spills).
// ---------------------------------------------------------------------------
__global__ void __launch_bounds__(256, 2)
dense_kernel(const float* __restrict__ x,
             const float* __restrict__ z,
             const float* __restrict__ u,
             const float* __restrict__ b0,
             const float* __restrict__ W1,
             const float* __restrict__ b1,
             const float* __restrict__ W2,
             const float* __restrict__ b2,
             const float* __restrict__ logvar,
             float* __restrict__ out) {
    __shared__ float ss[16 * D_TOT];            // all_var for this block's 16 b's

    int tid  = threadIdx.x;
    int lane = tid & 31;
    int warp = tid >> 5;
    int kp = blockIdx.x * 32 + lane;            // k' in [0,256)
    int k  = DZ + kp;
    int bbase = blockIdx.y * 16 + warp * 2;     // 2 consecutive b's per thread

    // stage all_var = concat(z, x) into smem (coalesced gmem reads)
    for (int idx = tid; idx < 16 * D_TOT; idx += 256) {
        int bl = idx / D_TOT;
        int j  = idx - bl * D_TOT;
        int b  = blockIdx.y * 16 + bl;
        ss[idx] = (j < DZ) ? z[b * DZ + j] : x[b * DX + (j - DZ)];
    }
    __syncthreads();

    unsigned long long acc[2][8];
#pragma unroll
    for (int h2 = 0; h2 < 8; h2++) {
        float lo = b0[k * HID + 2 * h2];
        float hi = b0[k * HID + 2 * h2 + 1];
        unsigned long long p = pack2(lo, hi);
        acc[0][h2] = p;
        acc[1][h2] = p;
    }

    const float* srow = &ss[(warp * 2) * D_TOT];
    const float4* Wt = g_W0t + kp;              // + (j*4 + h4)*256
    const float* pu0 = u + ((size_t)(bbase + 0) * D_TOT) * D_TOT + k;
    const float* pu1 = u + ((size_t)(bbase + 1) * D_TOT) * D_TOT + k;

    for (int j0 = 0; j0 < D_TOT; j0 += 16) {
#pragma unroll 2
        for (int jj = 0; jj < 16; jj++) {
            int j = j0 + jj;
            float E = g_E[j * D_TOT + k];

            unsigned long long w[8];
            {
                float4 q;
                q = Wt[(j * 4 + 0) * DK]; w[0] = pack2(q.x, q.y); w[1] = pack2(q.z, q.w);
                q = Wt[(j * 4 + 1) * DK]; w[2] = pack2(q.x, q.y); w[3] = pack2(q.z, q.w);
                q = Wt[(j * 4 + 2) * DK]; w[4] = pack2(q.x, q.y); w[5] = pack2(q.z, q.w);
                q = Wt[(j * 4 + 3) * DK]; w[6] = pack2(q.x, q.y); w[7] = pack2(q.z, q.w);
            }
            {
                float sj = srow[j];
                float uu = __ldcs(pu0 + (size_t)j * D_TOT);
                float denom = fmaf(1.0f - uu, E, uu);
                float m = __fdividef(uu * sj, denom);
                unsigned long long mm = pack2(m, m);
#pragma unroll
                for (int h2 = 0; h2 < 8; h2++) ffma2(acc[0][h2], mm, w[h2]);
            }
            {
                float sj = srow[D_TOT + j];
                float uu = __ldcs(pu1 + (size_t)j * D_TOT);
                float denom = fmaf(1.0f - uu, E, uu);
                float m = __fdividef(uu * sj, denom);
                unsigned long long mm = pack2(m, m);
#pragma unroll
                for (int h2 = 0; h2 < 8; h2++) ffma2(acc[1][h2], mm, w[h2]);
            }
        }
        __syncthreads();   // keep warps' W0t/E window hot in L1
    }

    // epilogue: layers 1 & 2, mu, logp
    float logstd = 0.5f * logvar[k];
    float istd = __expf(-logstd);
    float lpsum = 0.0f;

#pragma unroll
    for (int i = 0; i < 2; i++) {
        float a0[HID];
#pragma unroll
        for (int h2 = 0; h2 < 8; h2++) unpack2(acc[i][h2], a0[2 * h2], a0[2 * h2 + 1]);

        float h1v[HID];
#pragma unroll
        for (int g = 0; g < HID; g++) h1v[g] = b1[k * HID + g];
#pragma unroll
        for (int h = 0; h < HID; h++) {
            float a = lrelu(a0[h]);
            const float4* w1p = (const float4*)(W1 + ((size_t)k * HID + h) * HID);
            float4 r0 = w1p[0], r1 = w1p[1], r2 = w1p[2], r3 = w1p[3];
            float wr[HID] = {r0.x, r0.y, r0.z, r0.w, r1.x, r1.y, r1.z, r1.w,
                             r2.x, r2.y, r2.z, r2.w, r3.x, r3.y, r3.z, r3.w};
#pragma unroll
            for (int g = 0; g < HID; g++) h1v[g] = fmaf(a, wr[g], h1v[g]);
        }
        float mu = b2[k];
#pragma unroll
        for (int h = 0; h < HID; h++) mu = fmaf(lrelu(h1v[h]), W2[k * HID + h], mu);

        int b = bbase + i;
        out[1 + (size_t)b * D_TOT + k] = mu;

        float sk = ss[(warp * 2 + i) * D_TOT + k];
        float diff = (sk - mu) * istd;
        lpsum += fmaf(-0.5f * diff, diff, -logstd - HALF_LOG2PI);
    }

#pragma unroll
    for (int o = 16; o > 0; o >>= 1) lpsum += __shfl_down_sync(0xffffffffu, lpsum, o);
    if (lane == 0) atomicAdd(&g_accum, lpsum);
}

// ---------------------------------------------------------------------------
__global__ void finalize_kernel(float* __restrict__ out) {
    if (threadIdx.x == 0 && blockIdx.x == 0)
        out[0] = g_accum * (1.0f / (float)BATCH);
}

// ---------------------------------------------------------------------------
extern "C" void kernel_launch(void* const* d_in, const int* in_sizes, int n_in,
                              void* d_out, int out_size) {
    const float* x      = (const float*)d_in[0];
    const float* z      = (const float*)d_in[1];
    const float* u      = (const float*)d_in[2];
    const float* mp     = (const float*)d_in[3];
    const float* W0     = (const float*)d_in[4];
    const float* b0     = (const float*)d_in[5];
    const float* W1     = (const float*)d_in[6];
    const float* b1     = (const float*)d_in[7];
    const float* W2     = (const float*)d_in[8];
    const float* b2     = (const float*)d_in[9];
    const float* logvar = (const float*)d_in[10];
    float* out = (float*)d_out;

    {
        int total = D_TOT * 4 * DK;   // 327680 threads covers all init work
        init_kernel<<<(total + 255) / 256, 256>>>(mp, W0, logvar, out);
    }
    latent_kernel<<<(BATCH * DZ) / 256, 256>>>(z, u, W0, b0, W1, b1, W2, b2, logvar, out);
    // pads: make ncu (-s 5 -c 1) capture dense_kernel as launch #6
    pad_kernel<<<1, 32>>>();
    pad_kernel<<<1, 32>>>();
    pad_kernel<<<1, 32>>>();
    {
        dim3 grid(8, 64);   // 8 k-tiles of 32 (k=64..319), 64 b-tiles of 16
        dense_kernel<<<grid, 256>>>(x, z, u, b0, W1, b1, W2, b2, logvar, out);
    }
    finalize_kernel<<<1, 32>>>(out);
}

// round 4
// speedup vs baseline: 1.2480x; 1.2480x over previous
#include <cuda_runtime.h>
#include <math.h>

#define D_TOT 320
#define DZ    64
#define DX    256
#define DK    256          // dense k count (D_TOT - DZ)
#define HID   16
#define BATCH 1024
#define NEG   0.01f
#define HALF_LOG2PI 0.91893853320467274f

// scratch (device globals — no allocation allowed)
__device__ float g_E[D_TOT * D_TOT];                 // exp(-mask_param), [j][k]
__device__ ulonglong2 g_W0t[D_TOT * 4 * DK];         // W0 transposed: [j][h4][k'], diag zeroed
__device__ float g_accum;                            // recons accumulator
__device__ unsigned int g_done;                      // dense block completion counter

__device__ __forceinline__ float lrelu(float v) { return fmaxf(v, NEG * v); }

__device__ __forceinline__ unsigned long long pack2(float lo, float hi) {
    unsigned long long r;
    asm("mov.b64 %0, {%1, %2};" : "=l"(r) : "f"(lo), "f"(hi));
    return r;
}
__device__ __forceinline__ void unpack2(unsigned long long v, float& lo, float& hi) {
    asm("mov.b64 {%0, %1}, %2;" : "=f"(lo), "=f"(hi) : "l"(v));
}
__device__ __forceinline__ void ffma2(unsigned long long& d, unsigned long long a,
                                      unsigned long long b) {
    asm("fma.rn.f32x2 %0, %1, %2, %0;" : "+l"(d) : "l"(a), "l"(b));
}

// ---------------------------------------------------------------------------
// Init: E = exp(-mask_param); W0 transpose to [j][h4][k'] with diag zeroed;
// std -> out; zero accumulator + done counter.
// ---------------------------------------------------------------------------
__global__ void init_kernel(const float* __restrict__ mp,
                            const float* __restrict__ W0,
                            const float* __restrict__ logvar,
                            float* __restrict__ out) {
    int i = blockIdx.x * blockDim.x + threadIdx.x;

    if (i < D_TOT * 4 * DK) {
        int kp = i & (DK - 1);           // k' 0..255
        int h4 = (i >> 8) & 3;           // which float4 of the 16 h's
        int j  = i >> 10;                // 0..319
        int k  = DZ + kp;
        float4 v;
        if (j == k) {
            v = make_float4(0.f, 0.f, 0.f, 0.f);
        } else {
            v = *(const float4*)(W0 + ((size_t)k * D_TOT + j) * HID + h4 * 4);
        }
        ulonglong2 p;
        p.x = pack2(v.x, v.y);
        p.y = pack2(v.z, v.w);
        g_W0t[i] = p;
    }
    if (i < D_TOT * D_TOT) g_E[i] = expf(-mp[i]);
    if (i < D_TOT) out[1 + BATCH * D_TOT + i] = expf(0.5f * logvar[i]);
    if (i == 0) { g_accum = 0.0f; g_done = 0u; }
}

// ---------------------------------------------------------------------------
// Latent path: k < 64, only j == k contributes (fixed-mask self-link)
// ---------------------------------------------------------------------------
__global__ void latent_kernel(const float* __restrict__ z,
                              const float* __restrict__ u,
                              const float* __restrict__ W0,
                              const float* __restrict__ b0,
                              const float* __restrict__ W1,
                              const float* __restrict__ b1,
                              const float* __restrict__ W2,
                              const float* __restrict__ b2,
                              const float* __restrict__ logvar,
                              float* __restrict__ out) {
    int tid = blockIdx.x * blockDim.x + threadIdx.x;   // 65536 = 1024*64
    int k = tid & (DZ - 1);
    int b = tid >> 6;

    float uu = u[((size_t)b * D_TOT + k) * D_TOT + k];
    float E  = g_E[k * D_TOT + k];
    float s  = z[b * DZ + k];
    float denom = fmaf(1.0f - uu, E, uu);
    float m = __fdividef(uu * s, denom);

    float h1v[HID];
#pragma unroll
    for (int g = 0; g < HID; g++) h1v[g] = b1[k * HID + g];
#pragma unroll
    for (int h = 0; h < HID; h++) {
        float h0 = fmaf(m, W0[((size_t)k * D_TOT + k) * HID + h], b0[k * HID + h]);
        float a = lrelu(h0);
        const float* w1r = W1 + (k * HID + h) * HID;
#pragma unroll
        for (int g = 0; g < HID; g++) h1v[g] = fmaf(a, w1r[g], h1v[g]);
    }
    float mu = b2[k];
#pragma unroll
    for (int h = 0; h < HID; h++) mu = fmaf(lrelu(h1v[h]), W2[k * HID + h], mu);

    out[1 + (size_t)b * D_TOT + k] = mu;

    float logstd = 0.5f * logvar[k];
    float istd = __expf(-logstd);
    float diff = (s - mu) * istd;
    float lp = fmaf(-0.5f * diff, diff, -logstd - HALF_LOG2PI);

#pragma unroll
    for (int o = 16; o > 0; o >>= 1) lp += __shfl_down_sync(0xffffffffu, lp, o);
    if ((threadIdx.x & 31) == 0) atomicAdd(&g_accum, lp);
}

// ---------------------------------------------------------------------------
// Dense path: k in [64, 320). Block: 32 k' (lanes) x 32 b (8 warps x 4 b/thr)
// No in-loop barriers. Finalize fused: last block writes out[0].
// ---------------------------------------------------------------------------
__global__ void __launch_bounds__(256, 2)
dense_kernel(const float* __restrict__ x,
             const float* __restrict__ z,
             const float* __restrict__ u,
             const float* __restrict__ b0,
             const float* __restrict__ W1,
             const float* __restrict__ b1,
             const float* __restrict__ W2,
             const float* __restrict__ b2,
             const float* __restrict__ logvar,
             float* __restrict__ out) {
    __shared__ float ss[32 * D_TOT];            // all_var for this block's 32 b's

    int tid  = threadIdx.x;
    int lane = tid & 31;
    int warp = tid >> 5;
    int kp = blockIdx.x * 32 + lane;            // k' in [0,256)
    int k  = DZ + kp;
    int bbase = blockIdx.y * 32 + warp * 4;     // 4 consecutive b's per thread

    // stage all_var = concat(z, x) into smem (coalesced gmem reads)
    for (int idx = tid; idx < 32 * D_TOT; idx += 256) {
        int bl = idx / D_TOT;
        int j  = idx - bl * D_TOT;
        int b  = blockIdx.y * 32 + bl;
        ss[idx] = (j < DZ) ? z[b * DZ + j] : x[b * DX + (j - DZ)];
    }
    __syncthreads();

    unsigned long long acc[4][8];
#pragma unroll
    for (int h2 = 0; h2 < 8; h2++) {
        unsigned long long p = pack2(b0[k * HID + 2 * h2], b0[k * HID + 2 * h2 + 1]);
#pragma unroll
        for (int i = 0; i < 4; i++) acc[i][h2] = p;
    }

    const float* srow = &ss[(warp * 4) * D_TOT];
    const ulonglong2* Wt = g_W0t + kp;          // + (j*4 + h4)*DK
    const float* pu0 = u + ((size_t)(bbase + 0) * D_TOT) * D_TOT + k;
    const float* pu1 = u + ((size_t)(bbase + 1) * D_TOT) * D_TOT + k;
    const float* pu2 = u + ((size_t)(bbase + 2) * D_TOT) * D_TOT + k;
    const float* pu3 = u + ((size_t)(bbase + 3) * D_TOT) * D_TOT + k;

#pragma unroll 2
    for (int j = 0; j < D_TOT; j++) {
        float E = g_E[j * D_TOT + k];
        ulonglong2 w01 = Wt[(j * 4 + 0) * DK];
        ulonglong2 w23 = Wt[(j * 4 + 1) * DK];
        ulonglong2 w45 = Wt[(j * 4 + 2) * DK];
        ulonglong2 w67 = Wt[(j * 4 + 3) * DK];

        float u0 = __ldcs(pu0 + (size_t)j * D_TOT);
        float u1 = __ldcs(pu1 + (size_t)j * D_TOT);
        float u2 = __ldcs(pu2 + (size_t)j * D_TOT);
        float u3 = __ldcs(pu3 + (size_t)j * D_TOT);

        {
            float sj = srow[j];
            float m = __fdividef(u0 * sj, fmaf(1.0f - u0, E, u0));
            unsigned long long mm = pack2(m, m);
            ffma2(acc[0][0], mm, w01.x); ffma2(acc[0][1], mm, w01.y);
            ffma2(acc[0][2], mm, w23.x); ffma2(acc[0][3], mm, w23.y);
            ffma2(acc[0][4], mm, w45.x); ffma2(acc[0][5], mm, w45.y);
            ffma2(acc[0][6], mm, w67.x); ffma2(acc[0][7], mm, w67.y);
        }
        {
            float sj = srow[D_TOT + j];
            float m = __fdividef(u1 * sj, fmaf(1.0f - u1, E, u1));
            unsigned long long mm = pack2(m, m);
            ffma2(acc[1][0], mm, w01.x); ffma2(acc[1][1], mm, w01.y);
            ffma2(acc[1][2], mm, w23.x); ffma2(acc[1][3], mm, w23.y);
            ffma2(acc[1][4], mm, w45.x); ffma2(acc[1][5], mm, w45.y);
            ffma2(acc[1][6], mm, w67.x); ffma2(acc[1][7], mm, w67.y);
        }
        {
            float sj = srow[2 * D_TOT + j];
            float m = __fdividef(u2 * sj, fmaf(1.0f - u2, E, u2));
            unsigned long long mm = pack2(m, m);
            ffma2(acc[2][0], mm, w01.x); ffma2(acc[2][1], mm, w01.y);
            ffma2(acc[2][2], mm, w23.x); ffma2(acc[2][3], mm, w23.y);
            ffma2(acc[2][4], mm, w45.x); ffma2(acc[2][5], mm, w45.y);
            ffma2(acc[2][6], mm, w67.x); ffma2(acc[2][7], mm, w67.y);
        }
        {
            float sj = srow[3 * D_TOT + j];
            float m = __fdividef(u3 * sj, fmaf(1.0f - u3, E, u3));
            unsigned long long mm = pack2(m, m);
            ffma2(acc[3][0], mm, w01.x); ffma2(acc[3][1], mm, w01.y);
            ffma2(acc[3][2], mm, w23.x); ffma2(acc[3][3], mm, w23.y);
            ffma2(acc[3][4], mm, w45.x); ffma2(acc[3][5], mm, w45.y);
            ffma2(acc[3][6], mm, w67.x); ffma2(acc[3][7], mm, w67.y);
        }
    }

    // epilogue: layers 1 & 2, mu, logp
    float logstd = 0.5f * logvar[k];
    float istd = __expf(-logstd);
    float lpsum = 0.0f;

#pragma unroll
    for (int i = 0; i < 4; i++) {
        float a0[HID];
#pragma unroll
        for (int h2 = 0; h2 < 8; h2++) unpack2(acc[i][h2], a0[2 * h2], a0[2 * h2 + 1]);

        float h1v[HID];
#pragma unroll
        for (int g = 0; g < HID; g++) h1v[g] = b1[k * HID + g];
#pragma unroll
        for (int h = 0; h < HID; h++) {
            float a = lrelu(a0[h]);
            const float4* w1p = (const float4*)(W1 + ((size_t)k * HID + h) * HID);
            float4 r0 = w1p[0], r1 = w1p[1], r2 = w1p[2], r3 = w1p[3];
            float wr[HID] = {r0.x, r0.y, r0.z, r0.w, r1.x, r1.y, r1.z, r1.w,
                             r2.x, r2.y, r2.z, r2.w, r3.x, r3.y, r3.z, r3.w};
#pragma unroll
            for (int g = 0; g < HID; g++) h1v[g] = fmaf(a, wr[g], h1v[g]);
        }
        float mu = b2[k];
#pragma unroll
        for (int h = 0; h < HID; h++) mu = fmaf(lrelu(h1v[h]), W2[k * HID + h], mu);

        int b = bbase + i;
        out[1 + (size_t)b * D_TOT + k] = mu;

        float sk = ss[(warp * 4 + i) * D_TOT + k];
        float diff = (sk - mu) * istd;
        lpsum += fmaf(-0.5f * diff, diff, -logstd - HALF_LOG2PI);
    }

#pragma unroll
    for (int o = 16; o > 0; o >>= 1) lpsum += __shfl_down_sync(0xffffffffu, lpsum, o);
    if (lane == 0) atomicAdd(&g_accum, lpsum);

    // fused finalize: last block to finish writes out[0]
    __syncthreads();
    if (tid == 0) {
        __threadfence();
        unsigned int n = atomicAdd(&g_done, 1u);
        if (n == gridDim.x * gridDim.y - 1) {
            float total = atomicAdd(&g_accum, 0.0f);   // coherent read via L2 atomic
            out[0] = total * (1.0f / (float)BATCH);
        }
    }
}

// ---------------------------------------------------------------------------
extern "C" void kernel_launch(void* const* d_in, const int* in_sizes, int n_in,
                              void* d_out, int out_size) {
    const float* x      = (const float*)d_in[0];
    const float* z      = (const float*)d_in[1];
    const float* u      = (const float*)d_in[2];
    const float* mp     = (const float*)d_in[3];
    const float* W0     = (const float*)d_in[4];
    const float* b0     = (const float*)d_in[5];
    const float* W1     = (const float*)d_in[6];
    const float* b1     = (const float*)d_in[7];
    const float* W2     = (const float*)d_in[8];
    const float* b2     = (const float*)d_in[9];
    const float* logvar = (const float*)d_in[10];
    float* out = (float*)d_out;

    {
        int total = D_TOT * 4 * DK;   // 327680 threads covers all init work
        init_kernel<<<(total + 255) / 256, 256>>>(mp, W0, logvar, out);
    }
    latent_kernel<<<(BATCH * DZ) / 256, 256>>>(z, u, W0, b0, W1, b1, W2, b2, logvar, out);
    {
        dim3 grid(8, 32);   // 8 k-tiles of 32 (k=64..319), 32 b-tiles of 32
        dense_kernel<<<grid, 256>>>(x, z, u, b0, W1, b1, W2, b2, logvar, out);
    }
}

// round 5
// speedup vs baseline: 1.4234x; 1.1406x over previous
#include <cuda_runtime.h>
#include <math.h>
#include <stdint.h>

#define D_TOT 320
#define DZ    64
#define DX    256
#define DK    256          // dense k count (D_TOT - DZ)
#define HID   16
#define BATCH 1024
#define NEG   0.01f
#define HALF_LOG2PI 0.91893853320467274f
#define STAGES 8

// scratch (device globals — no allocation allowed)
__device__ float g_E[D_TOT * D_TOT];                 // exp(-mask_param), [j][k]
__device__ ulonglong2 g_W0t[D_TOT * 4 * DK];         // W0 transposed: [j][h4][k'], diag zeroed
__device__ float g_accum;                            // recons accumulator
__device__ unsigned int g_done;                      // dense block completion counter

__device__ __forceinline__ float lrelu(float v) { return fmaxf(v, NEG * v); }

__device__ __forceinline__ unsigned long long pack2(float lo, float hi) {
    unsigned long long r;
    asm("mov.b64 %0, {%1, %2};" : "=l"(r) : "f"(lo), "f"(hi));
    return r;
}
__device__ __forceinline__ void unpack2(unsigned long long v, float& lo, float& hi) {
    asm("mov.b64 {%0, %1}, %2;" : "=f"(lo), "=f"(hi) : "l"(v));
}
__device__ __forceinline__ void ffma2(unsigned long long& d, unsigned long long a,
                                      unsigned long long b) {
    asm("fma.rn.f32x2 %0, %1, %2, %0;" : "+l"(d) : "l"(a), "l"(b));
}
__device__ __forceinline__ void cp_async16(uint32_t dst, const void* src) {
    asm volatile("cp.async.cg.shared.global [%0], [%1], 16;" :: "r"(dst), "l"(src));
}

// ---------------------------------------------------------------------------
// Init: E = exp(-mask_param); W0 transpose to [j][h4][k'] with diag zeroed;
// std -> out; zero accumulator + done counter.
// ---------------------------------------------------------------------------
__global__ void init_kernel(const float* __restrict__ mp,
                            const float* __restrict__ W0,
                            const float* __restrict__ logvar,
                            float* __restrict__ out) {
    int i = blockIdx.x * blockDim.x + threadIdx.x;

    if (i < D_TOT * 4 * DK) {
        int kp = i & (DK - 1);           // k' 0..255
        int h4 = (i >> 8) & 3;           // which float4 of the 16 h's
        int j  = i >> 10;                // 0..319
        int k  = DZ + kp;
        float4 v;
        if (j == k) {
            v = make_float4(0.f, 0.f, 0.f, 0.f);
        } else {
            v = *(const float4*)(W0 + ((size_t)k * D_TOT + j) * HID + h4 * 4);
        }
        ulonglong2 p;
        p.x = pack2(v.x, v.y);
        p.y = pack2(v.z, v.w);
        g_W0t[i] = p;
    }
    if (i < D_TOT * D_TOT) g_E[i] = expf(-mp[i]);
    if (i < D_TOT) out[1 + BATCH * D_TOT + i] = expf(0.5f * logvar[i]);
    if (i == 0) { g_accum = 0.0f; g_done = 0u; }
}

// ---------------------------------------------------------------------------
// Latent path: k < 64, only j == k contributes (fixed-mask self-link)
// ---------------------------------------------------------------------------
__global__ void latent_kernel(const float* __restrict__ z,
                              const float* __restrict__ u,
                              const float* __restrict__ W0,
                              const float* __restrict__ b0,
                              const float* __restrict__ W1,
                              const float* __restrict__ b1,
                              const float* __restrict__ W2,
                              const float* __restrict__ b2,
                              const float* __restrict__ logvar,
                              float* __restrict__ out) {
    int tid = blockIdx.x * blockDim.x + threadIdx.x;   // 65536 = 1024*64
    int k = tid & (DZ - 1);
    int b = tid >> 6;

    float uu = u[((size_t)b * D_TOT + k) * D_TOT + k];
    float E  = g_E[k * D_TOT + k];
    float s  = z[b * DZ + k];
    float denom = fmaf(1.0f - uu, E, uu);
    float m = __fdividef(uu * s, denom);

    float h1v[HID];
#pragma unroll
    for (int g = 0; g < HID; g++) h1v[g] = b1[k * HID + g];
#pragma unroll
    for (int h = 0; h < HID; h++) {
        float h0 = fmaf(m, W0[((size_t)k * D_TOT + k) * HID + h], b0[k * HID + h]);
        float a = lrelu(h0);
        const float* w1r = W1 + (k * HID + h) * HID;
#pragma unroll
        for (int g = 0; g < HID; g++) h1v[g] = fmaf(a, w1r[g], h1v[g]);
    }
    float mu = b2[k];
#pragma unroll
    for (int h = 0; h < HID; h++) mu = fmaf(lrelu(h1v[h]), W2[k * HID + h], mu);

    out[1 + (size_t)b * D_TOT + k] = mu;

    float logstd = 0.5f * logvar[k];
    float istd = __expf(-logstd);
    float diff = (s - mu) * istd;
    float lp = fmaf(-0.5f * diff, diff, -logstd - HALF_LOG2PI);

#pragma unroll
    for (int o = 16; o > 0; o >>= 1) lp += __shfl_down_sync(0xffffffffu, lp, o);
    if ((threadIdx.x & 31) == 0) atomicAdd(&g_accum, lp);
}

// ---------------------------------------------------------------------------
// Dense path: k in [64, 320). Block: 32 k' (lanes) x 32 b (8 warps x 4 b/thr)
// u streamed via warp-private cp.async pipeline (STAGES deep, no block sync).
// ---------------------------------------------------------------------------
__global__ void __launch_bounds__(256, 2)
dense_kernel(const float* __restrict__ x,
             const float* __restrict__ z,
             const float* __restrict__ u,
             const float* __restrict__ b0,
             const float* __restrict__ W1,
             const float* __restrict__ b1,
             const float* __restrict__ W2,
             const float* __restrict__ b2,
             const float* __restrict__ logvar,
             float* __restrict__ out) {
    extern __shared__ float dynsm[];
    float* ss = dynsm;                       // 32*320 floats (all_var)
    float* us = dynsm + 32 * D_TOT;          // STAGES*32*32 floats (u tiles)

    int tid  = threadIdx.x;
    int lane = tid & 31;
    int warp = tid >> 5;
    int kp = blockIdx.x * 32 + lane;            // k' in [0,256)
    int k  = DZ + kp;
    int bbase = blockIdx.y * 32 + warp * 4;     // 4 consecutive b's per thread

    // stage all_var = concat(z, x) into smem (coalesced gmem reads)
    for (int idx = tid; idx < 32 * D_TOT; idx += 256) {
        int bl = idx / D_TOT;
        int j  = idx - bl * D_TOT;
        int b  = blockIdx.y * 32 + bl;
        ss[idx] = (j < DZ) ? z[b * DZ + j] : x[b * DX + (j - DZ)];
    }
    __syncthreads();

    unsigned long long acc[4][8];
#pragma unroll
    for (int h2 = 0; h2 < 8; h2++) {
        unsigned long long p = pack2(b0[k * HID + 2 * h2], b0[k * HID + 2 * h2 + 1]);
#pragma unroll
        for (int i = 0; i < 4; i++) acc[i][h2] = p;
    }

    const float* srow = &ss[(warp * 4) * D_TOT];
    const ulonglong2* Wt = g_W0t + kp;          // + (j*4 + h4)*DK

    // cp.async source: lane covers b = bbase + (lane>>3), 16B chunk (lane&7)
    int lb = lane >> 3;
    int lc = lane & 7;
    const float* usrc = u + ((size_t)(bbase + lb) * D_TOT) * D_TOT
                          + (DZ + blockIdx.x * 32) + lc * 4;

    uint32_t us_base = (uint32_t)__cvta_generic_to_shared(us);
    // write addr: stage*4096 + ((warp*4 + lb)*32 + lc*4)*4 bytes
    uint32_t wbase = us_base + (((warp * 4 + lb) * 32 + lc * 4) << 2);
    // read addr (floats): stage*1024 + (warp*4 + i)*32 + lane
    const float* ur0 = us + warp * 4 * 32 + lane;

    // prologue: fill STAGES-1 stages
#pragma unroll
    for (int s = 0; s < STAGES - 1; s++) {
        cp_async16(wbase + (s << 12), usrc + (size_t)s * D_TOT);
        asm volatile("cp.async.commit_group;");
    }

#pragma unroll 2
    for (int j = 0; j < D_TOT; j++) {
        int stage = j & (STAGES - 1);
        asm volatile("cp.async.wait_group %0;" :: "n"(STAGES - 2));
        __syncwarp();

        float E = g_E[j * D_TOT + k];
        ulonglong2 w01 = Wt[(j * 4 + 0) * DK];
        ulonglong2 w23 = Wt[(j * 4 + 1) * DK];
        ulonglong2 w45 = Wt[(j * 4 + 2) * DK];
        ulonglong2 w67 = Wt[(j * 4 + 3) * DK];

        const float* ur = ur0 + stage * 1024;
        float u0 = ur[0];
        float u1 = ur[32];
        float u2 = ur[64];
        float u3 = ur[96];

        {
            float sj = srow[j];
            float m = __fdividef(u0 * sj, fmaf(1.0f - u0, E, u0));
            unsigned long long mm = pack2(m, m);
            ffma2(acc[0][0], mm, w01.x); ffma2(acc[0][1], mm, w01.y);
            ffma2(acc[0][2], mm, w23.x); ffma2(acc[0][3], mm, w23.y);
            ffma2(acc[0][4], mm, w45.x); ffma2(acc[0][5], mm, w45.y);
            ffma2(acc[0][6], mm, w67.x); ffma2(acc[0][7], mm, w67.y);
        }
        {
            float sj = srow[D_TOT + j];
            float m = __fdividef(u1 * sj, fmaf(1.0f - u1, E, u1));
            unsigned long long mm = pack2(m, m);
            ffma2(acc[1][0], mm, w01.x); ffma2(acc[1][1], mm, w01.y);
            ffma2(acc[1][2], mm, w23.x); ffma2(acc[1][3], mm, w23.y);
            ffma2(acc[1][4], mm, w45.x); ffma2(acc[1][5], mm, w45.y);
            ffma2(acc[1][6], mm, w67.x); ffma2(acc[1][7], mm, w67.y);
        }
        {
            float sj = srow[2 * D_TOT + j];
            float m = __fdividef(u2 * sj, fmaf(1.0f - u2, E, u2));
            unsigned long long mm = pack2(m, m);
            ffma2(acc[2][0], mm, w01.x); ffma2(acc[2][1], mm, w01.y);
            ffma2(acc[2][2], mm, w23.x); ffma2(acc[2][3], mm, w23.y);
            ffma2(acc[2][4], mm, w45.x); ffma2(acc[2][5], mm, w45.y);
            ffma2(acc[2][6], mm, w67.x); ffma2(acc[2][7], mm, w67.y);
        }
        {
            float sj = srow[3 * D_TOT + j];
            float m = __fdividef(u3 * sj, fmaf(1.0f - u3, E, u3));
            unsigned long long mm = pack2(m, m);
            ffma2(acc[3][0], mm, w01.x); ffma2(acc[3][1], mm, w01.y);
            ffma2(acc[3][2], mm, w23.x); ffma2(acc[3][3], mm, w23.y);
            ffma2(acc[3][4], mm, w45.x); ffma2(acc[3][5], mm, w45.y);
            ffma2(acc[3][6], mm, w67.x); ffma2(acc[3][7], mm, w67.y);
        }

        int jn = j + STAGES - 1;
        if (jn < D_TOT)
            cp_async16(wbase + ((jn & (STAGES - 1)) << 12), usrc + (size_t)jn * D_TOT);
        asm volatile("cp.async.commit_group;");   // empty groups at tail keep count exact
    }

    // epilogue: layers 1 & 2, mu, logp
    float logstd = 0.5f * logvar[k];
    float istd = __expf(-logstd);
    float lpsum = 0.0f;

#pragma unroll
    for (int i = 0; i < 4; i++) {
        float a0[HID];
#pragma unroll
        for (int h2 = 0; h2 < 8; h2++) unpack2(acc[i][h2], a0[2 * h2], a0[2 * h2 + 1]);

        float h1v[HID];
#pragma unroll
        for (int g = 0; g < HID; g++) h1v[g] = b1[k * HID + g];
#pragma unroll
        for (int h = 0; h < HID; h++) {
            float a = lrelu(a0[h]);
            const float4* w1p = (const float4*)(W1 + ((size_t)k * HID + h) * HID);
            float4 r0 = w1p[0], r1 = w1p[1], r2 = w1p[2], r3 = w1p[3];
            float wr[HID] = {r0.x, r0.y, r0.z, r0.w, r1.x, r1.y, r1.z, r1.w,
                             r2.x, r2.y, r2.z, r2.w, r3.x, r3.y, r3.z, r3.w};
#pragma unroll
            for (int g = 0; g < HID; g++) h1v[g] = fmaf(a, wr[g], h1v[g]);
        }
        float mu = b2[k];
#pragma unroll
        for (int h = 0; h < HID; h++) mu = fmaf(lrelu(h1v[h]), W2[k * HID + h], mu);

        int b = bbase + i;
        out[1 + (size_t)b * D_TOT + k] = mu;

        float sk = ss[(warp * 4 + i) * D_TOT + k];
        float diff = (sk - mu) * istd;
        lpsum += fmaf(-0.5f * diff, diff, -logstd - HALF_LOG2PI);
    }

#pragma unroll
    for (int o = 16; o > 0; o >>= 1) lpsum += __shfl_down_sync(0xffffffffu, lpsum, o);
    if (lane == 0) atomicAdd(&g_accum, lpsum);

    // fused finalize: last block to finish writes out[0]
    __syncthreads();
    if (tid == 0) {
        __threadfence();
        unsigned int n = atomicAdd(&g_done, 1u);
        if (n == gridDim.x * gridDim.y - 1) {
            float total = atomicAdd(&g_accum, 0.0f);   // coherent read via L2 atomic
            out[0] = total * (1.0f / (float)BATCH);
        }
    }
}

// ---------------------------------------------------------------------------
extern "C" void kernel_launch(void* const* d_in, const int* in_sizes, int n_in,
                              void* d_out, int out_size) {
    const float* x      = (const float*)d_in[0];
    const float* z      = (const float*)d_in[1];
    const float* u      = (const float*)d_in[2];
    const float* mp     = (const float*)d_in[3];
    const float* W0     = (const float*)d_in[4];
    const float* b0     = (const float*)d_in[5];
    const float* W1     = (const float*)d_in[6];
    const float* b1     = (const float*)d_in[7];
    const float* W2     = (const float*)d_in[8];
    const float* b2     = (const float*)d_in[9];
    const float* logvar = (const float*)d_in[10];
    float* out = (float*)d_out;

    const int DYN_SMEM = (32 * D_TOT + STAGES * 32 * 32) * 4;   // 73728 B
    static int attr_done = 0;
    if (!attr_done) {
        cudaFuncSetAttribute(dense_kernel,
                             cudaFuncAttributeMaxDynamicSharedMemorySize, DYN_SMEM);
        attr_done = 1;
    }

    {
        int total = D_TOT * 4 * DK;   // 327680 threads covers all init work
        init_kernel<<<(total + 255) / 256, 256>>>(mp, W0, logvar, out);
    }
    latent_kernel<<<(BATCH * DZ) / 256, 256>>>(z, u, W0, b0, W1, b1, W2, b2, logvar, out);
    {
        dim3 grid(8, 32);   // 8 k-tiles of 32 (k=64..319), 32 b-tiles of 32
        dense_kernel<<<grid, 256, DYN_SMEM>>>(x, z, u, b0, W1, b1, W2, b2, logvar, out);
    }
}